// round 15
// baseline (speedup 1.0000x reference)
#include <cuda_runtime.h>
#include <cuda_bf16.h>
#include <math.h>
#include <cstdint>

#define NROWS 65536
#define DIN   480
#define H0D   512
#define GDIM  384
#define TAILG 296

// ================= scratch (device globals; no allocation) =================
__device__ __nv_bfloat16 gY0b[(size_t)NROWS * 128];       // y0 /sqrt(128)
__device__ __nv_bfloat16 gY1b[(size_t)3 * NROWS * 64];    // [m][row][64]
__device__ __nv_bfloat16 gY2b[(size_t)5 * NROWS * 64];    // [m][row][64] (only k<32 used)
__device__ __nv_bfloat16 gSb [(size_t)NROWS * 512];       // silu(h0)/sqrt(512)
// gates in MMA-native layout: [sg 0..5][tile 0..511][wid 0..7][idx16 0..15][lane 0..31] float2
__device__ float         gG3 [(size_t)6 * 512 * 128 * 64];
__device__ float         gO1 [(size_t)3 * NROWS * 64];    // o1 (scales folded)
__device__ float         gO2 [(size_t)5 * NROWS * 32];    // o2
// transposed bf16 weights  Wt[p][k]
__device__ __nv_bfloat16 gWt0[(size_t)896 * 128];
__device__ __nv_bfloat16 gWt1[(size_t)256 * 64];
__device__ __nv_bfloat16 gWt2[(size_t)128 * 64];          // k 32..63 zero (unused)
__device__ __nv_bfloat16 gVt0[(size_t)128 * 512];
__device__ __nv_bfloat16 gVt1[(size_t)64 * 256];
__device__ __nv_bfloat16 gVt2[(size_t)32 * 128];

// ================= helpers =================
__device__ __forceinline__ uint32_t smem_to_u32(const void* p) {
    uint32_t a;
    asm("{ .reg .u64 t; cvta.to.shared.u64 t, %1; cvt.u32.u64 %0, t; }" : "=r"(a) : "l"(p));
    return a;
}
#define SWZ(b) ((b) ^ (((b) >> 3) & 0x70))

__device__ __forceinline__ void cp16(uint32_t saddr, const void* g) {
    asm volatile("cp.async.cg.shared.global [%0], [%1], 16;" :: "r"(saddr), "l"(g));
}
__device__ __forceinline__ void cp_commit() {
    asm volatile("cp.async.commit_group;" ::: "memory");
}
__device__ __forceinline__ void cp_wait2() {
    asm volatile("cp.async.wait_group 2;" ::: "memory");
}
__device__ __forceinline__ void cp_wait1() {
    asm volatile("cp.async.wait_group 1;" ::: "memory");
}
__device__ __forceinline__ void prefetch_l1(const void* p) {
    asm volatile("prefetch.global.L1 [%0];" :: "l"(p));
}

__device__ __forceinline__ void ldsm_x4(uint32_t* r, uint32_t addr) {
    asm volatile("ldmatrix.sync.aligned.m8n8.x4.shared.b16 {%0,%1,%2,%3}, [%4];"
        : "=r"(r[0]), "=r"(r[1]), "=r"(r[2]), "=r"(r[3]) : "r"(addr));
}
__device__ __forceinline__ void ldsm_x2(uint32_t* r, uint32_t addr) {
    asm volatile("ldmatrix.sync.aligned.m8n8.x2.shared.b16 {%0,%1}, [%2];"
        : "=r"(r[0]), "=r"(r[1]) : "r"(addr));
}
__device__ __forceinline__ void mma16816(float* d, const uint32_t* a, const uint32_t* b) {
    asm volatile(
        "mma.sync.aligned.m16n8k16.row.col.f32.bf16.bf16.f32 "
        "{%0,%1,%2,%3}, {%4,%5,%6,%7}, {%8,%9}, {%0,%1,%2,%3};"
        : "+f"(d[0]), "+f"(d[1]), "+f"(d[2]), "+f"(d[3])
        : "r"(a[0]), "r"(a[1]), "r"(a[2]), "r"(a[3]), "r"(b[0]), "r"(b[1]));
}
__device__ __forceinline__ float sigmf(float v) { return 1.0f / (1.0f + __expf(-v)); }

// ================= kernel 0: weight convert+transpose =================
__global__ void __launch_bounds__(256) convert_w(
    const float* __restrict__ W0, const float* __restrict__ W1, const float* __restrict__ W2,
    const float* __restrict__ V0, const float* __restrict__ V1, const float* __restrict__ V2)
{
    int i = blockIdx.x * 256 + threadIdx.x;
    if (i < 114688) {                       // Wt0[896][128] <- W0[128][896]
        int p = i / 128, k = i % 128;
        gWt0[i] = __float2bfloat16(W0[k * 896 + p]);
    } else if ((i -= 114688) < 16384) {     // Wt1[256][64] <- W1[64][256]
        int p = i / 64, k = i % 64;
        gWt1[i] = __float2bfloat16(W1[k * 256 + p]);
    } else if ((i -= 16384) < 8192) {       // Wt2[128][64] <- W2[32][128], pad
        int p = i / 64, k = i % 64;
        gWt2[i] = (k < 32) ? __float2bfloat16(W2[k * 128 + p]) : __float2bfloat16(0.f);
    } else if ((i -= 8192) < 65536) {       // Vt0[128][512] <- V0[512][128]
        int p = i / 512, k = i % 512;
        gVt0[i] = __float2bfloat16(V0[k * 128 + p]);
    } else if ((i -= 65536) < 16384) {      // Vt1[64][256] <- V1[256][64]
        int p = i / 256, k = i % 256;
        gVt1[i] = __float2bfloat16(V1[k * 64 + p]);
    } else if ((i -= 16384) < 4096) {       // Vt2[32][128] <- V2[128][32]
        int p = i / 128, k = i % 128;
        gVt2[i] = __float2bfloat16(V2[k * 32 + p]);
    }
}

// ================= kernel 1: norms (one warp per row) =================
__global__ void __launch_bounds__(256) norm_kernel(
    const float* __restrict__ x,  const float* __restrict__ nw0,
    const float* __restrict__ nb0, const float* __restrict__ nw1,
    const float* __restrict__ nw2)
{
    const int warp = threadIdx.x >> 5;
    const int lane = threadIdx.x & 31;
    const int row  = blockIdx.x * 8 + warp;
    const float* xr = x + (size_t)row * DIN;

    float4 v0 = ((const float4*)xr)[lane];
    float s = v0.x + v0.y + v0.z + v0.w;
    float q = v0.x*v0.x + v0.y*v0.y + v0.z*v0.z + v0.w*v0.w;
#pragma unroll
    for (int o = 16; o; o >>= 1) {
        s += __shfl_xor_sync(0xffffffffu, s, o);
        q += __shfl_xor_sync(0xffffffffu, q, o);
    }
    const float mu   = s * (1.0f / 128.0f);
    const float rstd = rsqrtf(q * (1.0f / 128.0f) - mu * mu + 1e-8f);

    float ss1 = 0.f, ss2 = 0.f;
    const float4* xr2 = (const float4*)(xr + 128);
#pragma unroll
    for (int j = lane; j < 88; j += 32) {
        float4 v = xr2[j];
        float d = v.x*v.x + v.y*v.y + v.z*v.z + v.w*v.w;
        if (j < 48) ss1 += d; else ss2 += d;
    }
#pragma unroll
    for (int o = 16; o; o >>= 1) {
        ss1 += __shfl_xor_sync(0xffffffffu, ss1, o);
        ss2 += __shfl_xor_sync(0xffffffffu, ss2, o);
    }
    const float inv = rsqrtf(0.5f * (ss1 * (1.f/192.f) + ss2 * (1.f/160.f)) + 1e-8f);

    const float invS0 = 0.08838834764831845f;
    float4 w = ((const float4*)nw0)[lane];
    float4 b = ((const float4*)nb0)[lane];
    __nv_bfloat16* y0 = gY0b + (size_t)row * 128 + lane * 4;
    y0[0] = __float2bfloat16(((v0.x - mu) * rstd * w.x + b.x) * invS0);
    y0[1] = __float2bfloat16(((v0.y - mu) * rstd * w.y + b.y) * invS0);
    y0[2] = __float2bfloat16(((v0.z - mu) * rstd * w.z + b.z) * invS0);
    y0[3] = __float2bfloat16(((v0.w - mu) * rstd * w.w + b.w) * invS0);

#pragma unroll
    for (int t = 0; t < 2; ++t) {
        int u = lane + t * 32;
        float c = inv * nw1[u] * 0.125f;
#pragma unroll
        for (int m = 0; m < 3; ++m)
            gY1b[((size_t)m * NROWS + row) * 64 + u] = __float2bfloat16(xr[128 + 3*u + m] * c);
    }
    {
        int u = lane;
        float c = inv * nw2[u] * 0.17677669529663689f;
#pragma unroll
        for (int m = 0; m < 5; ++m)
            gY2b[((size_t)m * NROWS + row) * 64 + u] =
                __float2bfloat16(xr[320 + 5*u + m] * c);
    }
}

// ================= HMMA GEMM body (persistent + cp.async pipeline) =========
// EPI 0: h0 -> silu/gate (BRES: B slab smem-resident) ; EPI 3: o0 + residual.
template<int KdA, int NT, int EPI, bool BRES>
__device__ __forceinline__ void mma_body(
    int t0, int tstr, int pb,
    const float* __restrict__ bias, const float* __restrict__ X,
    const float* __restrict__ alphap, float* __restrict__ Out)
{
    constexpr int NCH   = KdA / 64;
    constexpr int WT_N  = NT / 4;
    constexpr int NI    = WT_N / 8;
    constexpr int MI    = 4;
    constexpr int SAB   = 128 * 128;                 // A chunk bytes
    constexpr int SBB   = NT * 128;                  // B chunk bytes
    constexpr int STAGE = BRES ? SAB : (SAB + SBB);  // per-pipeline-stage bytes
    constexpr int OFF_B = 3 * SAB;                   // BRES: resident B planes
    constexpr int DEPTH = 3;
    constexpr int NTILES = NROWS / 128;

    extern __shared__ __align__(16) char dsm[];
    const uint32_t sbase = smem_to_u32(dsm);

    const int tid  = threadIdx.x;
    const int lane = tid & 31;
    const int wid  = tid >> 5;
    const int wm   = wid >> 2;
    const int wn   = wid & 3;

    const __nv_bfloat16* gA  = (EPI == 0) ? gY0b : gSb;
    const __nv_bfloat16* gBw = (EPI == 0) ? gWt0 : gVt0;

    const int my_tiles = (t0 < NTILES) ? ((NTILES - 1 - t0) / tstr + 1) : 0;
    const int my_iters = my_tiles * NCH;

    auto issue_load = [&](int idx) {
        const int tile = t0 + (idx / NCH) * tstr;
        const int ch   = idx % NCH;
        const uint32_t st = sbase + (uint32_t)(idx % DEPTH) * STAGE;
        const __nv_bfloat16* Ab = gA + (size_t)(tile * 128) * KdA + ch * 64;
#pragma unroll
        for (int t = 0; t < 4; ++t) {
            int i2 = tid + t * 256;
            int r = i2 >> 3, v = i2 & 7;
            cp16(st + SWZ(r * 128 + v * 16), Ab + (size_t)r * KdA + v * 8);
        }
        if (!BRES) {
            const __nv_bfloat16* Bb = gBw + (size_t)pb * KdA + ch * 64;
#pragma unroll
            for (int t = 0; t < NT / 32; ++t) {
                int i2 = tid + t * 256;
                int r = i2 >> 3, v = i2 & 7;
                cp16(st + SAB + SWZ(r * 128 + v * 16), Bb + (size_t)r * KdA + v * 8);
            }
        }
    };

    float acc[MI][NI][4];
#pragma unroll
    for (int i = 0; i < MI; ++i)
#pragma unroll
        for (int j = 0; j < NI; ++j)
#pragma unroll
            for (int r = 0; r < 4; ++r) acc[i][j][r] = 0.f;

    const int a_rowoff = (lane & 7) + ((lane >> 3) & 1) * 8;
    const int a_khalf  = lane >> 4;
    const int laneb    = lane & 15;
    const int b_rowoff = laneb & 7;
    const int b_khalf  = laneb >> 3;
    const float ta = (EPI == 3) ? tanhf(alphap[0]) : 0.0f;

    // prologue: BRES loads resident B (all NCH chunks) in group 0.
    // Total 16B xfers = NT rows x NCH*8 per row = NT*NCH*8; passes = NT*NCH/32.
    if (BRES && my_iters > 0) {
        const __nv_bfloat16* Bb = gBw + (size_t)pb * KdA;
#pragma unroll
        for (int t = 0; t < (NT * NCH) / 32; ++t) {
            int i2 = tid + t * 256;
            int r = i2 >> 4, v = i2 & 15;         // r < NT, v < 16
            int ch = v >> 3, v8 = v & 7;
            cp16(sbase + OFF_B + (uint32_t)ch * SBB + SWZ(r * 128 + v8 * 16),
                 Bb + (size_t)r * KdA + ch * 64 + v8 * 8);
        }
    }
#pragma unroll
    for (int i = 0; i < DEPTH; ++i) {
        if (i < my_iters) issue_load(i);
        cp_commit();
    }

#pragma unroll 1
    for (int it = 0; it < my_iters; ++it) {
        cp_wait2();
        __syncthreads();

        const uint32_t st_a = sbase + (uint32_t)(it % DEPTH) * STAGE;
        const uint32_t st_b = BRES ? (sbase + OFF_B + (uint32_t)(it % NCH) * SBB)
                                   : (st_a + SAB);
#pragma unroll
        for (int ks = 0; ks < 4; ++ks) {
            const int kbyte = ks * 32;
            uint32_t af[MI][4], bf[NI][2];
#pragma unroll
            for (int mi = 0; mi < MI; ++mi) {
                int r = wm * 64 + mi * 16 + a_rowoff;
                ldsm_x4(af[mi], st_a + SWZ(r * 128 + kbyte + a_khalf * 16));
            }
#pragma unroll
            for (int ni = 0; ni < NI; ++ni) {
                int r = wn * WT_N + ni * 8 + b_rowoff;
                ldsm_x2(bf[ni], st_b + SWZ(r * 128 + kbyte + b_khalf * 16));
            }
#pragma unroll
            for (int mi = 0; mi < MI; ++mi)
#pragma unroll
                for (int ni = 0; ni < NI; ++ni)
                    mma16816(acc[mi][ni], af[mi], bf[ni]);
        }

        if ((it % NCH) == NCH - 1) {
            const int tile = t0 + (it / NCH) * tstr;
            const int rowBase = tile * 128;
#pragma unroll
            for (int mi = 0; mi < MI; ++mi) {
#pragma unroll
                for (int ni = 0; ni < NI; ++ni) {
                    const int p0 = pb + wn * WT_N + ni * 8 + (lane & 3) * 2;
#pragma unroll
                    for (int rp = 0; rp < 2; ++rp) {
                        const int row = rowBase + wm * 64 + mi * 16 + (lane >> 2) + rp * 8;
                        float v0 = acc[mi][ni][rp * 2];
                        float v1 = acc[mi][ni][rp * 2 + 1];
                        if (EPI == 0) {
                            float h0 = v0 + bias[p0];
                            float h1 = v1 + bias[p0 + 1];
                            if (p0 < H0D) {   // uniform per block
                                __nv_bfloat162 pk;
                                pk.x = __float2bfloat16(h0 * sigmf(h0) * 0.04419417382415922f);
                                pk.y = __float2bfloat16(h1 * sigmf(h1) * 0.04419417382415922f);
                                *(__nv_bfloat162*)(gSb + (size_t)row * 512 + p0) = pk;
                            } else {
                                // gate -> MMA-native layout for zo consumers
                                float2 pk = {sigmf(h0), sigmf(h1)};
                                int gcol = p0 - H0D;
                                int sg = gcol >> 6, pl = gcol & 63;
                                int lr = row & 127;
                                int wm_z = lr >> 6, mi_z = (lr >> 4) & 3,
                                    rp_z = (lr >> 3) & 1, lq = lr & 7;
                                int wn_z = pl >> 4, ni_z = (pl >> 3) & 1,
                                    l2 = (pl >> 1) & 3;
                                int wid_z = wm_z * 4 + wn_z;
                                int lane_z = lq * 4 + l2;
                                int idx = mi_z * 4 + ni_z * 2 + rp_z;
                                size_t off = (((size_t)sg * NTILES + tile) << 13)
                                           + wid_z * 1024 + (idx * 32 + lane_z) * 2;
                                *(float2*)(gG3 + off) = pk;
                            }
                        } else {
                            size_t o = (size_t)row * DIN + p0;
                            float2 xv = *(const float2*)(X + o);
                            float2 pk = {xv.x + ta * (v0 + bias[p0]),
                                         xv.y + ta * (v1 + bias[p0 + 1])};
                            *(float2*)(Out + o) = pk;
                        }
                        acc[mi][ni][rp * 2] = 0.f;
                        acc[mi][ni][rp * 2 + 1] = 0.f;
                    }
                }
            }
        }

        __syncthreads();
        if (it + DEPTH < my_iters) issue_load(it + DEPTH);
        cp_commit();
    }
}

__global__ void __launch_bounds__(256, 2) mma0_kernel(const float* __restrict__ bias) {
    mma_body<128, 128, 0, true>(blockIdx.x, gridDim.x, blockIdx.y * 128,
                                bias, nullptr, nullptr, nullptr);
}

// ================= fused z + down-projection body per spectral branch ======
// Slab pipeline: stage(s) consumes zacc, zacc recomputed for s+1 BEFORE
// oMMA(s) so each inter-barrier window carries 64 back-to-back HMMA.
template<int M, int BR>   // BR=1: H=256,K=64 ; BR=2: H=128,K=32
__device__ __forceinline__ void zo_body(int t0, int tstr)
{
    constexpr int NSLAB  = (BR == 1) ? 4 : 2;       // H / 64
    constexpr int KSY    = (BR == 1) ? 4 : 2;       // k16 steps of the z GEMM
    constexpr int OW     = (BR == 1) ? 64 : 32;     // o columns
    constexpr int ONI    = OW / 32;                 // 2 / 1
    constexpr int SGOF   = (BR == 1) ? 0 : 4;       // global gate-slab offset
    constexpr int WROWS  = (BR == 1) ? 256 : 128;
    constexpr int VROWS  = OW;
    constexpr int VCB    = VROWS * 128;             // bytes per Vt chunk
    constexpr int OFF_W  = 0;
    constexpr int OFF_V  = OFF_W + WROWS * 128;
    constexpr int OFF_Y  = OFF_V + NSLAB * VCB;
    constexpr int YB     = 128 * 128;
    constexpr int OFF_Z  = OFF_Y + 2 * YB;
    constexpr int NTILES = NROWS / 128;

    extern __shared__ __align__(16) char dsm[];
    const uint32_t sbase = smem_to_u32(dsm);

    const int tid  = threadIdx.x;
    const int wid  = tid >> 5;
    const int lane = tid & 31;
    const int wm   = wid >> 2;
    const int wn   = wid & 3;

    const __nv_bfloat16* gA  = (BR == 1) ? gY1b : gY2b;
    const __nv_bfloat16* gWt = (BR == 1) ? gWt1 : gWt2;
    const __nv_bfloat16* gVt = (BR == 1) ? gVt1 : gVt2;
    float* gO = (BR == 1) ? gO1 : gO2;
    const float SCALE = (BR == 1) ? 0.0625f : 0.08838834764831845f;

    const int my_tiles = (t0 < NTILES) ? ((NTILES - 1 - t0) / tstr + 1) : 0;
    const int my_iters = my_tiles * M;

    auto issue_y = [&](int j) {
        const int tile = t0 + (j / M) * tstr;
        const int mm   = j % M;
        const __nv_bfloat16* Ab = gA + ((size_t)mm * NROWS + tile * 128) * 64;
        const uint32_t yb = sbase + OFF_Y + (uint32_t)(j & 1) * YB;
        if (KSY == 4) {
#pragma unroll
            for (int t = 0; t < 4; ++t) {
                int i2 = tid + t * 256;
                int r = i2 >> 3, v = i2 & 7;
                cp16(yb + SWZ(r * 128 + v * 16), Ab + (size_t)r * 64 + v * 8);
            }
        } else {
#pragma unroll
            for (int t = 0; t < 2; ++t) {
                int i2 = tid + t * 256;
                int r = i2 >> 2, v = i2 & 3;
                cp16(yb + SWZ(r * 128 + v * 16), Ab + (size_t)r * 64 + v * 8);
            }
        }
    };

    // prologue: weights + Vt + Y(0) in group0, Y(1) in group1
    if (my_iters > 0) {
        if (BR == 1) {
#pragma unroll
            for (int t = 0; t < 8; ++t) {       // Wt1: 256 rows x 8 xfers
                int i2 = tid + t * 256;
                int r = i2 >> 3, v = i2 & 7;
                cp16(sbase + OFF_W + SWZ(r * 128 + v * 16), gWt + (size_t)r * 64 + v * 8);
            }
#pragma unroll
            for (int t = 0; t < 8; ++t) {       // Vt1: 4 chunks x 64 rows x 8 xfers
                int i2 = tid + t * 256;
                int s = i2 >> 9, p = (i2 >> 3) & 63, v = i2 & 7;
                cp16(sbase + OFF_V + s * VCB + SWZ(p * 128 + v * 16),
                     gVt + (size_t)p * 256 + s * 64 + v * 8);
            }
        } else {
#pragma unroll
            for (int t = 0; t < 2; ++t) {       // Wt2: 128 rows x 4 xfers (K=32)
                int i2 = tid + t * 256;
                int r = i2 >> 2, v = i2 & 3;
                cp16(sbase + OFF_W + SWZ(r * 128 + v * 16), gWt + (size_t)r * 64 + v * 8);
            }
#pragma unroll
            for (int t = 0; t < 2; ++t) {       // Vt2: 2 chunks x 32 rows x 8 xfers
                int i2 = tid + t * 256;
                int s = i2 >> 8, p = (i2 >> 3) & 31, v = i2 & 7;
                cp16(sbase + OFF_V + s * VCB + SWZ(p * 128 + v * 16),
                     gVt + (size_t)p * 128 + s * 64 + v * 8);
            }
        }
        issue_y(0);
    }
    cp_commit();
    if (1 < my_iters) issue_y(1);
    cp_commit();

    float oacc[4][ONI][4];
#pragma unroll
    for (int i = 0; i < 4; ++i)
#pragma unroll
        for (int j = 0; j < ONI; ++j)
#pragma unroll
            for (int r = 0; r < 4; ++r) oacc[i][j][r] = 0.f;

    const int a_rowoff = (lane & 7) + ((lane >> 3) & 1) * 8;
    const int a_khalf  = lane >> 4;
    const int laneb    = lane & 15;
    const int b_rowoff = laneb & 7;
    const int b_khalf  = laneb >> 3;

#pragma unroll 1
    for (int j = 0; j < my_iters; ++j) {
        cp_wait1();
        __syncthreads();

        const uint32_t yb = sbase + OFF_Y + (uint32_t)(j & 1) * YB;
        const int tile = t0 + (j / M) * tstr;
        const int rowBase = tile * 128;

        float zacc[4][2][4];
        // z slab MMA helper (zeroes + accumulates into zacc)
        auto zmma = [&](int s) {
#pragma unroll
            for (int i = 0; i < 4; ++i)
#pragma unroll
                for (int n = 0; n < 2; ++n)
#pragma unroll
                    for (int r = 0; r < 4; ++r) zacc[i][n][r] = 0.f;
            const size_t gblk = ((size_t)(SGOF + s) * NTILES + tile) << 13;
            prefetch_l1((const char*)(gG3 + gblk) + wid * 4096 + lane * 128);
#pragma unroll
            for (int ks = 0; ks < KSY; ++ks) {
                const int kbyte = ks * 32;
                uint32_t af[4][4], bf[2][2];
#pragma unroll
                for (int mi = 0; mi < 4; ++mi) {
                    int r = wm * 64 + mi * 16 + a_rowoff;
                    ldsm_x4(af[mi], yb + SWZ(r * 128 + kbyte + a_khalf * 16));
                }
#pragma unroll
                for (int ni = 0; ni < 2; ++ni) {
                    int r = s * 64 + wn * 16 + ni * 8 + b_rowoff;
                    ldsm_x2(bf[ni], sbase + OFF_W + SWZ(r * 128 + kbyte + b_khalf * 16));
                }
#pragma unroll
                for (int mi = 0; mi < 4; ++mi)
#pragma unroll
                    for (int ni = 0; ni < 2; ++ni)
                        mma16816(zacc[mi][ni], af[mi], bf[ni]);
            }
        };

        zmma(0);

#pragma unroll 1
        for (int s = 0; s < NSLAB; ++s) {
            __syncthreads();               // prior o-MMA reads of Z done
            // ---- gate + scale, stage bf16 z slab (coalesced gate loads) ----
            {
                const size_t gblk = ((size_t)(SGOF + s) * NTILES + tile) << 13;
                const float2* Gt = (const float2*)(gG3 + gblk) + wid * 512 + lane;
#pragma unroll
                for (int mi = 0; mi < 4; ++mi) {
#pragma unroll
                    for (int ni = 0; ni < 2; ++ni) {
                        const int pl = wn * 16 + ni * 8 + (lane & 3) * 2;
#pragma unroll
                        for (int rp = 0; rp < 2; ++rp) {
                            const int lrow = wm * 64 + mi * 16 + (lane >> 2) + rp * 8;
                            float2 g = Gt[(mi * 4 + ni * 2 + rp) * 32];
                            __nv_bfloat162 pk;
                            pk.x = __float2bfloat16(zacc[mi][ni][rp * 2]     * g.x * SCALE);
                            pk.y = __float2bfloat16(zacc[mi][ni][rp * 2 + 1] * g.y * SCALE);
                            *(uint32_t*)(dsm + OFF_Z + SWZ(lrow * 128 + pl * 2)) =
                                *(uint32_t*)&pk;
                        }
                    }
                }
            }
            __syncthreads();               // Z visible

            if (s + 1 < NSLAB) zmma(s + 1);   // next z slab (Y/W only)

            // ---- o MMA: zstage (128x64) @ Vt chunk s, accumulate ----
#pragma unroll
            for (int ks2 = 0; ks2 < 4; ++ks2) {
                const int kbyte = ks2 * 32;
                uint32_t af2[4][4], bfo[ONI][2];
#pragma unroll
                for (int mi = 0; mi < 4; ++mi) {
                    int r = wm * 64 + mi * 16 + a_rowoff;
                    ldsm_x4(af2[mi], sbase + OFF_Z + SWZ(r * 128 + kbyte + a_khalf * 16));
                }
#pragma unroll
                for (int ni = 0; ni < ONI; ++ni) {
                    int rv = wn * (OW / 4) + ni * 8 + b_rowoff;
                    ldsm_x2(bfo[ni], sbase + OFF_V + s * VCB
                                     + SWZ(rv * 128 + kbyte + b_khalf * 16));
                }
#pragma unroll
                for (int mi = 0; mi < 4; ++mi)
#pragma unroll
                    for (int ni = 0; ni < ONI; ++ni)
                        mma16816(oacc[mi][ni], af2[mi], bfo[ni]);
            }
        }

        // ---- store o ----
        {
            const int mm = j % M;
#pragma unroll
            for (int mi = 0; mi < 4; ++mi) {
#pragma unroll
                for (int ni = 0; ni < ONI; ++ni) {
                    const int p0 = wn * (OW / 4) + ni * 8 + (lane & 3) * 2;
#pragma unroll
                    for (int rp = 0; rp < 2; ++rp) {
                        const int row = rowBase + wm * 64 + mi * 16 + (lane >> 2) + rp * 8;
                        float2 pk = {oacc[mi][ni][rp * 2], oacc[mi][ni][rp * 2 + 1]};
                        *(float2*)(gO + ((size_t)mm * NROWS + row) * OW + p0) = pk;
                        oacc[mi][ni][rp * 2] = 0.f;
                        oacc[mi][ni][rp * 2 + 1] = 0.f;
                    }
                }
            }
        }

        if (j + 2 < my_iters) issue_y(j + 2);
        cp_commit();
    }
}

// ================= fused tail: zo1 | zo2 | o0 in one launch =================
__global__ void __launch_bounds__(256, 2) tail_kernel(
    const float* __restrict__ c0, const float* __restrict__ X,
    const float* __restrict__ alphap, float* __restrict__ Out)
{
    const int phase = blockIdx.x / TAILG;
    const int bx    = blockIdx.x % TAILG;
    if (phase == 0)      zo_body<3, 1>(bx, TAILG);
    else if (phase == 1) zo_body<5, 2>(bx, TAILG);
    else                 mma_body<512, 128, 3, false>(bx, TAILG, 0, c0, X, alphap, Out);
}

// ================= final combine (smem transpose, coalesced) ================
__global__ void __launch_bounds__(256) combine_kernel(
    const float* __restrict__ x, const float* __restrict__ alphap,
    float* __restrict__ out)
{
    __shared__ float sO1[8][3][66];
    __shared__ float sO2[8][5][34];
    const int warp = threadIdx.x >> 5;
    const int lane = threadIdx.x & 31;
    const int row  = blockIdx.x * 8 + warp;
    const float ta = tanhf(alphap[0]);
    const float* xr = x + (size_t)row * DIN;
    float* outr = out + (size_t)row * DIN;

    // coalesced loads of this row's o1/o2 into smem
#pragma unroll
    for (int t = 0; t < 6; ++t) {          // 3*64 = 192 floats
        int idx = lane + t * 32;
        int m = idx >> 6, w = idx & 63;
        sO1[warp][m][w] = gO1[((size_t)m * NROWS + row) * 64 + w];
    }
#pragma unroll
    for (int t = 0; t < 5; ++t) {          // 5*32 = 160 floats
        int idx = lane + t * 32;
        int m = idx >> 5, w = idx & 31;
        sO2[warp][m][w] = gO2[((size_t)m * NROWS + row) * 32 + w];
    }
    __syncwarp();

#pragma unroll
    for (int t = 0; t < 6; ++t) {          // cols 128..319
        int c = 128 + lane + t * 32;
        int d = c - 128;
        outr[c] = xr[c] + ta * sO1[warp][d % 3][d / 3];
    }
#pragma unroll
    for (int t = 0; t < 5; ++t) {          // cols 320..479
        int c = 320 + lane + t * 32;
        int d = c - 320;
        outr[c] = xr[c] + ta * sO2[warp][d % 5][d / 5];
    }
}

// ================= launch =================
extern "C" void kernel_launch(void* const* d_in, const int* in_sizes, int n_in,
                              void* d_out, int out_size) {
    const float* x     = (const float*)d_in[0];
    const float* nw0   = (const float*)d_in[1];
    const float* nb0   = (const float*)d_in[2];
    const float* nw1   = (const float*)d_in[3];
    const float* nw2   = (const float*)d_in[4];
    const float* W0    = (const float*)d_in[5];
    const float* b0    = (const float*)d_in[6];
    const float* W1    = (const float*)d_in[7];
    const float* W2    = (const float*)d_in[8];
    const float* V0    = (const float*)d_in[9];
    const float* c0    = (const float*)d_in[10];
    const float* V1    = (const float*)d_in[11];
    const float* V2    = (const float*)d_in[12];
    const float* alpha = (const float*)d_in[13];
    float* out = (float*)d_out;

    constexpr int SM0   = 3 * 128 * 128 + 2 * 128 * 128;            // 80 KB (BRES)
    constexpr int SMZ1  = 256*128 + 4*64*128 + 2*128*128 + 128*128; // 112 KB
    cudaFuncSetAttribute(mma0_kernel, cudaFuncAttributeMaxDynamicSharedMemorySize, SM0);
    cudaFuncSetAttribute(tail_kernel, cudaFuncAttributeMaxDynamicSharedMemorySize, SMZ1);

    convert_w<<<880, 256>>>(W0, W1, W2, V0, V1, V2);
    norm_kernel<<<NROWS / 8, 256>>>(x, nw0, nb0, nw1, nw2);

    // stage 1: h0 -> silu/gates (B slab smem-resident)
    mma0_kernel<<<dim3(84, 7, 1), 256, SM0>>>(b0);
    // fused tail: zo1 + zo2 + o0 (all depend only on h0/norm)
    tail_kernel<<<3 * TAILG, 256, SMZ1>>>(c0, x, alpha, out);
    // residual gather for cols 128..479
    combine_kernel<<<NROWS / 8, 256>>>(x, alpha, out);
}

// round 16
// speedup vs baseline: 1.0130x; 1.0130x over previous
#include <cuda_runtime.h>
#include <cuda_bf16.h>
#include <math.h>
#include <cstdint>

#define NROWS 65536
#define DIN   480
#define H0D   512
#define GDIM  384
#define TAILG 296

// ================= scratch (device globals; no allocation) =================
__device__ __nv_bfloat16 gY0b[(size_t)NROWS * 128];       // y0 /sqrt(128)
__device__ __nv_bfloat16 gY1b[(size_t)3 * NROWS * 64];    // [m][row][64]
__device__ __nv_bfloat16 gY2b[(size_t)5 * NROWS * 64];    // [m][row][64] (only k<32 used)
__device__ __nv_bfloat16 gSb [(size_t)NROWS * 512];       // silu(h0)/sqrt(512)
// gates in MMA-native layout: [sg 0..5][tile 0..511][wid 0..7][idx16 0..15][lane 0..31] float2
__device__ float         gG3 [(size_t)6 * 512 * 128 * 64];
__device__ float         gO1 [(size_t)3 * NROWS * 64];    // o1 (scales folded)
__device__ float         gO2 [(size_t)5 * NROWS * 32];    // o2
// transposed bf16 weights  Wt[p][k]
__device__ __nv_bfloat16 gWt0[(size_t)896 * 128];
__device__ __nv_bfloat16 gWt1[(size_t)256 * 64];
__device__ __nv_bfloat16 gWt2[(size_t)128 * 64];          // k 32..63 zero (unused)
__device__ __nv_bfloat16 gVt0[(size_t)128 * 512];
__device__ __nv_bfloat16 gVt1[(size_t)64 * 256];
__device__ __nv_bfloat16 gVt2[(size_t)32 * 128];

// ================= helpers =================
__device__ __forceinline__ uint32_t smem_to_u32(const void* p) {
    uint32_t a;
    asm("{ .reg .u64 t; cvta.to.shared.u64 t, %1; cvt.u32.u64 %0, t; }" : "=r"(a) : "l"(p));
    return a;
}
#define SWZ(b) ((b) ^ (((b) >> 3) & 0x70))

__device__ __forceinline__ void cp16(uint32_t saddr, const void* g) {
    asm volatile("cp.async.cg.shared.global [%0], [%1], 16;" :: "r"(saddr), "l"(g));
}
__device__ __forceinline__ void cp_commit() {
    asm volatile("cp.async.commit_group;" ::: "memory");
}
__device__ __forceinline__ void cp_wait2() {
    asm volatile("cp.async.wait_group 2;" ::: "memory");
}
__device__ __forceinline__ void cp_wait1() {
    asm volatile("cp.async.wait_group 1;" ::: "memory");
}
__device__ __forceinline__ void prefetch_l1(const void* p) {
    asm volatile("prefetch.global.L1 [%0];" :: "l"(p));
}

__device__ __forceinline__ void ldsm_x4(uint32_t* r, uint32_t addr) {
    asm volatile("ldmatrix.sync.aligned.m8n8.x4.shared.b16 {%0,%1,%2,%3}, [%4];"
        : "=r"(r[0]), "=r"(r[1]), "=r"(r[2]), "=r"(r[3]) : "r"(addr));
}
__device__ __forceinline__ void ldsm_x2(uint32_t* r, uint32_t addr) {
    asm volatile("ldmatrix.sync.aligned.m8n8.x2.shared.b16 {%0,%1}, [%2];"
        : "=r"(r[0]), "=r"(r[1]) : "r"(addr));
}
__device__ __forceinline__ void mma16816(float* d, const uint32_t* a, const uint32_t* b) {
    asm volatile(
        "mma.sync.aligned.m16n8k16.row.col.f32.bf16.bf16.f32 "
        "{%0,%1,%2,%3}, {%4,%5,%6,%7}, {%8,%9}, {%0,%1,%2,%3};"
        : "+f"(d[0]), "+f"(d[1]), "+f"(d[2]), "+f"(d[3])
        : "r"(a[0]), "r"(a[1]), "r"(a[2]), "r"(a[3]), "r"(b[0]), "r"(b[1]));
}
__device__ __forceinline__ float sigmf(float v) { return 1.0f / (1.0f + __expf(-v)); }

// ================= kernel 0: weight convert+transpose =================
__global__ void __launch_bounds__(256) convert_w(
    const float* __restrict__ W0, const float* __restrict__ W1, const float* __restrict__ W2,
    const float* __restrict__ V0, const float* __restrict__ V1, const float* __restrict__ V2)
{
    int i = blockIdx.x * 256 + threadIdx.x;
    if (i < 114688) {                       // Wt0[896][128] <- W0[128][896]
        int p = i / 128, k = i % 128;
        gWt0[i] = __float2bfloat16(W0[k * 896 + p]);
    } else if ((i -= 114688) < 16384) {     // Wt1[256][64] <- W1[64][256]
        int p = i / 64, k = i % 64;
        gWt1[i] = __float2bfloat16(W1[k * 256 + p]);
    } else if ((i -= 16384) < 8192) {       // Wt2[128][64] <- W2[32][128], pad
        int p = i / 64, k = i % 64;
        gWt2[i] = (k < 32) ? __float2bfloat16(W2[k * 128 + p]) : __float2bfloat16(0.f);
    } else if ((i -= 8192) < 65536) {       // Vt0[128][512] <- V0[512][128]
        int p = i / 512, k = i % 512;
        gVt0[i] = __float2bfloat16(V0[k * 128 + p]);
    } else if ((i -= 65536) < 16384) {      // Vt1[64][256] <- V1[256][64]
        int p = i / 256, k = i % 256;
        gVt1[i] = __float2bfloat16(V1[k * 64 + p]);
    } else if ((i -= 16384) < 4096) {       // Vt2[32][128] <- V2[128][32]
        int p = i / 128, k = i % 128;
        gVt2[i] = __float2bfloat16(V2[k * 32 + p]);
    }
}

// ================= kernel 1: norms (one warp per row) =================
__global__ void __launch_bounds__(256) norm_kernel(
    const float* __restrict__ x,  const float* __restrict__ nw0,
    const float* __restrict__ nb0, const float* __restrict__ nw1,
    const float* __restrict__ nw2)
{
    const int warp = threadIdx.x >> 5;
    const int lane = threadIdx.x & 31;
    const int row  = blockIdx.x * 8 + warp;
    const float* xr = x + (size_t)row * DIN;

    float4 v0 = ((const float4*)xr)[lane];
    float s = v0.x + v0.y + v0.z + v0.w;
    float q = v0.x*v0.x + v0.y*v0.y + v0.z*v0.z + v0.w*v0.w;
#pragma unroll
    for (int o = 16; o; o >>= 1) {
        s += __shfl_xor_sync(0xffffffffu, s, o);
        q += __shfl_xor_sync(0xffffffffu, q, o);
    }
    const float mu   = s * (1.0f / 128.0f);
    const float rstd = rsqrtf(q * (1.0f / 128.0f) - mu * mu + 1e-8f);

    float ss1 = 0.f, ss2 = 0.f;
    const float4* xr2 = (const float4*)(xr + 128);
#pragma unroll
    for (int j = lane; j < 88; j += 32) {
        float4 v = xr2[j];
        float d = v.x*v.x + v.y*v.y + v.z*v.z + v.w*v.w;
        if (j < 48) ss1 += d; else ss2 += d;
    }
#pragma unroll
    for (int o = 16; o; o >>= 1) {
        ss1 += __shfl_xor_sync(0xffffffffu, ss1, o);
        ss2 += __shfl_xor_sync(0xffffffffu, ss2, o);
    }
    const float inv = rsqrtf(0.5f * (ss1 * (1.f/192.f) + ss2 * (1.f/160.f)) + 1e-8f);

    const float invS0 = 0.08838834764831845f;
    float4 w = ((const float4*)nw0)[lane];
    float4 b = ((const float4*)nb0)[lane];
    __nv_bfloat16* y0 = gY0b + (size_t)row * 128 + lane * 4;
    y0[0] = __float2bfloat16(((v0.x - mu) * rstd * w.x + b.x) * invS0);
    y0[1] = __float2bfloat16(((v0.y - mu) * rstd * w.y + b.y) * invS0);
    y0[2] = __float2bfloat16(((v0.z - mu) * rstd * w.z + b.z) * invS0);
    y0[3] = __float2bfloat16(((v0.w - mu) * rstd * w.w + b.w) * invS0);

#pragma unroll
    for (int t = 0; t < 2; ++t) {
        int u = lane + t * 32;
        float c = inv * nw1[u] * 0.125f;
#pragma unroll
        for (int m = 0; m < 3; ++m)
            gY1b[((size_t)m * NROWS + row) * 64 + u] = __float2bfloat16(xr[128 + 3*u + m] * c);
    }
    {
        int u = lane;
        float c = inv * nw2[u] * 0.17677669529663689f;
#pragma unroll
        for (int m = 0; m < 5; ++m)
            gY2b[((size_t)m * NROWS + row) * 64 + u] =
                __float2bfloat16(xr[320 + 5*u + m] * c);
    }
}

// ================= HMMA GEMM body (persistent + cp.async pipeline) =========
// EPI 0: h0 -> silu/gate (BRES: B slab smem-resident) ; EPI 3: o0 + residual.
template<int KdA, int NT, int EPI, bool BRES>
__device__ __forceinline__ void mma_body(
    int t0, int tstr, int pb,
    const float* __restrict__ bias, const float* __restrict__ X,
    const float* __restrict__ alphap, float* __restrict__ Out)
{
    constexpr int NCH   = KdA / 64;
    constexpr int WT_N  = NT / 4;
    constexpr int NI    = WT_N / 8;
    constexpr int MI    = 4;
    constexpr int SAB   = 128 * 128;                 // A chunk bytes
    constexpr int SBB   = NT * 128;                  // B chunk bytes
    constexpr int STAGE = BRES ? SAB : (SAB + SBB);  // per-pipeline-stage bytes
    constexpr int OFF_B = 3 * SAB;                   // BRES: resident B planes
    constexpr int DEPTH = 3;
    constexpr int NTILES = NROWS / 128;

    extern __shared__ __align__(16) char dsm[];
    const uint32_t sbase = smem_to_u32(dsm);

    const int tid  = threadIdx.x;
    const int lane = tid & 31;
    const int wid  = tid >> 5;
    const int wm   = wid >> 2;
    const int wn   = wid & 3;

    const __nv_bfloat16* gA  = (EPI == 0) ? gY0b : gSb;
    const __nv_bfloat16* gBw = (EPI == 0) ? gWt0 : gVt0;

    const int my_tiles = (t0 < NTILES) ? ((NTILES - 1 - t0) / tstr + 1) : 0;
    const int my_iters = my_tiles * NCH;

    auto issue_load = [&](int idx) {
        const int tile = t0 + (idx / NCH) * tstr;
        const int ch   = idx % NCH;
        const uint32_t st = sbase + (uint32_t)(idx % DEPTH) * STAGE;
        const __nv_bfloat16* Ab = gA + (size_t)(tile * 128) * KdA + ch * 64;
#pragma unroll
        for (int t = 0; t < 4; ++t) {
            int i2 = tid + t * 256;
            int r = i2 >> 3, v = i2 & 7;
            cp16(st + SWZ(r * 128 + v * 16), Ab + (size_t)r * KdA + v * 8);
        }
        if (!BRES) {
            const __nv_bfloat16* Bb = gBw + (size_t)pb * KdA + ch * 64;
#pragma unroll
            for (int t = 0; t < NT / 32; ++t) {
                int i2 = tid + t * 256;
                int r = i2 >> 3, v = i2 & 7;
                cp16(st + SAB + SWZ(r * 128 + v * 16), Bb + (size_t)r * KdA + v * 8);
            }
        }
    };

    float acc[MI][NI][4];
#pragma unroll
    for (int i = 0; i < MI; ++i)
#pragma unroll
        for (int j = 0; j < NI; ++j)
#pragma unroll
            for (int r = 0; r < 4; ++r) acc[i][j][r] = 0.f;

    const int a_rowoff = (lane & 7) + ((lane >> 3) & 1) * 8;
    const int a_khalf  = lane >> 4;
    const int laneb    = lane & 15;
    const int b_rowoff = laneb & 7;
    const int b_khalf  = laneb >> 3;
    const float ta = (EPI == 3) ? tanhf(alphap[0]) : 0.0f;

    // prologue: BRES loads resident B (all NCH chunks) in group 0.
    // Total 16B xfers = NT rows x (NCH*8) = NT*NCH*8; passes = NT*NCH/32.
    if (BRES && my_iters > 0) {
        const __nv_bfloat16* Bb = gBw + (size_t)pb * KdA;
#pragma unroll
        for (int t = 0; t < (NT * NCH) / 32; ++t) {
            int i2 = tid + t * 256;
            int r = i2 >> 4, v = i2 & 15;         // r < NT, v < 16
            int ch = v >> 3, v8 = v & 7;
            cp16(sbase + OFF_B + (uint32_t)ch * SBB + SWZ(r * 128 + v8 * 16),
                 Bb + (size_t)r * KdA + ch * 64 + v8 * 8);
        }
    }
#pragma unroll
    for (int i = 0; i < DEPTH; ++i) {
        if (i < my_iters) issue_load(i);
        cp_commit();
    }

#pragma unroll 1
    for (int it = 0; it < my_iters; ++it) {
        cp_wait2();
        __syncthreads();

        const uint32_t st_a = sbase + (uint32_t)(it % DEPTH) * STAGE;
        const uint32_t st_b = BRES ? (sbase + OFF_B + (uint32_t)(it % NCH) * SBB)
                                   : (st_a + SAB);
#pragma unroll
        for (int ks = 0; ks < 4; ++ks) {
            const int kbyte = ks * 32;
            uint32_t af[MI][4], bf[NI][2];
#pragma unroll
            for (int mi = 0; mi < MI; ++mi) {
                int r = wm * 64 + mi * 16 + a_rowoff;
                ldsm_x4(af[mi], st_a + SWZ(r * 128 + kbyte + a_khalf * 16));
            }
#pragma unroll
            for (int ni = 0; ni < NI; ++ni) {
                int r = wn * WT_N + ni * 8 + b_rowoff;
                ldsm_x2(bf[ni], st_b + SWZ(r * 128 + kbyte + b_khalf * 16));
            }
#pragma unroll
            for (int mi = 0; mi < MI; ++mi)
#pragma unroll
                for (int ni = 0; ni < NI; ++ni)
                    mma16816(acc[mi][ni], af[mi], bf[ni]);
        }

        if ((it % NCH) == NCH - 1) {
            const int tile = t0 + (it / NCH) * tstr;
            const int rowBase = tile * 128;
#pragma unroll
            for (int mi = 0; mi < MI; ++mi) {
#pragma unroll
                for (int ni = 0; ni < NI; ++ni) {
                    const int p0 = pb + wn * WT_N + ni * 8 + (lane & 3) * 2;
#pragma unroll
                    for (int rp = 0; rp < 2; ++rp) {
                        const int row = rowBase + wm * 64 + mi * 16 + (lane >> 2) + rp * 8;
                        float v0 = acc[mi][ni][rp * 2];
                        float v1 = acc[mi][ni][rp * 2 + 1];
                        if (EPI == 0) {
                            float h0 = v0 + bias[p0];
                            float h1 = v1 + bias[p0 + 1];
                            if (p0 < H0D) {   // uniform per block
                                __nv_bfloat162 pk;
                                pk.x = __float2bfloat16(h0 * sigmf(h0) * 0.04419417382415922f);
                                pk.y = __float2bfloat16(h1 * sigmf(h1) * 0.04419417382415922f);
                                *(__nv_bfloat162*)(gSb + (size_t)row * 512 + p0) = pk;
                            } else {
                                // gate -> MMA-native layout for zo consumers
                                float2 pk = {sigmf(h0), sigmf(h1)};
                                int gcol = p0 - H0D;
                                int sg = gcol >> 6, pl = gcol & 63;
                                int lr = row & 127;
                                int wm_z = lr >> 6, mi_z = (lr >> 4) & 3,
                                    rp_z = (lr >> 3) & 1, lq = lr & 7;
                                int wn_z = pl >> 4, ni_z = (pl >> 3) & 1,
                                    l2 = (pl >> 1) & 3;
                                int wid_z = wm_z * 4 + wn_z;
                                int lane_z = lq * 4 + l2;
                                int idx = mi_z * 4 + ni_z * 2 + rp_z;
                                size_t off = (((size_t)sg * NTILES + tile) << 13)
                                           + wid_z * 1024 + (idx * 32 + lane_z) * 2;
                                *(float2*)(gG3 + off) = pk;
                            }
                        } else {
                            size_t o = (size_t)row * DIN + p0;
                            float2 xv = *(const float2*)(X + o);
                            float2 pk = {xv.x + ta * (v0 + bias[p0]),
                                         xv.y + ta * (v1 + bias[p0 + 1])};
                            *(float2*)(Out + o) = pk;
                        }
                        acc[mi][ni][rp * 2] = 0.f;
                        acc[mi][ni][rp * 2 + 1] = 0.f;
                    }
                }
            }
        }

        __syncthreads();
        if (it + DEPTH < my_iters) issue_load(it + DEPTH);
        cp_commit();
    }
}

__global__ void __launch_bounds__(256, 2) mma0_kernel(const float* __restrict__ bias) {
    mma_body<128, 128, 0, true>(blockIdx.x, gridDim.x, blockIdx.y * 128,
                                bias, nullptr, nullptr, nullptr);
}

// ================= fused z + down-projection body per spectral branch ======
// (R13 structure: zMMA -> stage -> oMMA per slab; no cross-slab pipelining.)
template<int M, int BR>   // BR=1: H=256,K=64 ; BR=2: H=128,K=32
__device__ __forceinline__ void zo_body(int t0, int tstr)
{
    constexpr int NSLAB  = (BR == 1) ? 4 : 2;       // H / 64
    constexpr int KSY    = (BR == 1) ? 4 : 2;       // k16 steps of the z GEMM
    constexpr int OW     = (BR == 1) ? 64 : 32;     // o columns
    constexpr int ONI    = OW / 32;                 // 2 / 1
    constexpr int SGOF   = (BR == 1) ? 0 : 4;       // global gate-slab offset
    constexpr int WROWS  = (BR == 1) ? 256 : 128;
    constexpr int VROWS  = OW;
    constexpr int VCB    = VROWS * 128;             // bytes per Vt chunk
    constexpr int OFF_W  = 0;
    constexpr int OFF_V  = OFF_W + WROWS * 128;
    constexpr int OFF_Y  = OFF_V + NSLAB * VCB;
    constexpr int YB     = 128 * 128;
    constexpr int OFF_Z  = OFF_Y + 2 * YB;
    constexpr int NTILES = NROWS / 128;

    extern __shared__ __align__(16) char dsm[];
    const uint32_t sbase = smem_to_u32(dsm);

    const int tid  = threadIdx.x;
    const int wid  = tid >> 5;
    const int lane = tid & 31;
    const int wm   = wid >> 2;
    const int wn   = wid & 3;

    const __nv_bfloat16* gA  = (BR == 1) ? gY1b : gY2b;
    const __nv_bfloat16* gWt = (BR == 1) ? gWt1 : gWt2;
    const __nv_bfloat16* gVt = (BR == 1) ? gVt1 : gVt2;
    float* gO = (BR == 1) ? gO1 : gO2;
    const float SCALE = (BR == 1) ? 0.0625f : 0.08838834764831845f;

    const int my_tiles = (t0 < NTILES) ? ((NTILES - 1 - t0) / tstr + 1) : 0;
    const int my_iters = my_tiles * M;

    auto issue_y = [&](int j) {
        const int tile = t0 + (j / M) * tstr;
        const int mm   = j % M;
        const __nv_bfloat16* Ab = gA + ((size_t)mm * NROWS + tile * 128) * 64;
        const uint32_t yb = sbase + OFF_Y + (uint32_t)(j & 1) * YB;
        if (KSY == 4) {
#pragma unroll
            for (int t = 0; t < 4; ++t) {
                int i2 = tid + t * 256;
                int r = i2 >> 3, v = i2 & 7;
                cp16(yb + SWZ(r * 128 + v * 16), Ab + (size_t)r * 64 + v * 8);
            }
        } else {
#pragma unroll
            for (int t = 0; t < 2; ++t) {
                int i2 = tid + t * 256;
                int r = i2 >> 2, v = i2 & 3;
                cp16(yb + SWZ(r * 128 + v * 16), Ab + (size_t)r * 64 + v * 8);
            }
        }
    };

    // prologue: weights + Vt + Y(0) in group0, Y(1) in group1
    if (my_iters > 0) {
        if (BR == 1) {
#pragma unroll
            for (int t = 0; t < 8; ++t) {       // Wt1: 256 rows x 8 xfers
                int i2 = tid + t * 256;
                int r = i2 >> 3, v = i2 & 7;
                cp16(sbase + OFF_W + SWZ(r * 128 + v * 16), gWt + (size_t)r * 64 + v * 8);
            }
#pragma unroll
            for (int t = 0; t < 8; ++t) {       // Vt1: 4 chunks x 64 rows x 8 xfers
                int i2 = tid + t * 256;
                int s = i2 >> 9, p = (i2 >> 3) & 63, v = i2 & 7;
                cp16(sbase + OFF_V + s * VCB + SWZ(p * 128 + v * 16),
                     gVt + (size_t)p * 256 + s * 64 + v * 8);
            }
        } else {
#pragma unroll
            for (int t = 0; t < 2; ++t) {       // Wt2: 128 rows x 4 xfers (K=32)
                int i2 = tid + t * 256;
                int r = i2 >> 2, v = i2 & 3;
                cp16(sbase + OFF_W + SWZ(r * 128 + v * 16), gWt + (size_t)r * 64 + v * 8);
            }
#pragma unroll
            for (int t = 0; t < 2; ++t) {       // Vt2: 2 chunks x 32 rows x 8 xfers
                int i2 = tid + t * 256;
                int s = i2 >> 8, p = (i2 >> 3) & 31, v = i2 & 7;
                cp16(sbase + OFF_V + s * VCB + SWZ(p * 128 + v * 16),
                     gVt + (size_t)p * 128 + s * 64 + v * 8);
            }
        }
        issue_y(0);
    }
    cp_commit();
    if (1 < my_iters) issue_y(1);
    cp_commit();

    float oacc[4][ONI][4];
#pragma unroll
    for (int i = 0; i < 4; ++i)
#pragma unroll
        for (int j = 0; j < ONI; ++j)
#pragma unroll
            for (int r = 0; r < 4; ++r) oacc[i][j][r] = 0.f;

    const int a_rowoff = (lane & 7) + ((lane >> 3) & 1) * 8;
    const int a_khalf  = lane >> 4;
    const int laneb    = lane & 15;
    const int b_rowoff = laneb & 7;
    const int b_khalf  = laneb >> 3;

#pragma unroll 1
    for (int j = 0; j < my_iters; ++j) {
        cp_wait1();
        __syncthreads();

        const uint32_t yb = sbase + OFF_Y + (uint32_t)(j & 1) * YB;
        const int tile = t0 + (j / M) * tstr;
        const int rowBase = tile * 128;

#pragma unroll 1
        for (int s = 0; s < NSLAB; ++s) {
            const size_t gblk = ((size_t)(SGOF + s) * NTILES + tile) << 13;  // floats
            const float2* Gt = (const float2*)(gG3 + gblk) + wid * 512 + lane;
            prefetch_l1((const char*)(gG3 + gblk) + wid * 4096 + lane * 128);

            float zacc[4][2][4];
#pragma unroll
            for (int i = 0; i < 4; ++i)
#pragma unroll
                for (int n = 0; n < 2; ++n)
#pragma unroll
                    for (int r = 0; r < 4; ++r) zacc[i][n][r] = 0.f;

            // ---- z slab MMA ----
#pragma unroll
            for (int ks = 0; ks < KSY; ++ks) {
                const int kbyte = ks * 32;
                uint32_t af[4][4], bf[2][2];
#pragma unroll
                for (int mi = 0; mi < 4; ++mi) {
                    int r = wm * 64 + mi * 16 + a_rowoff;
                    ldsm_x4(af[mi], yb + SWZ(r * 128 + kbyte + a_khalf * 16));
                }
#pragma unroll
                for (int ni = 0; ni < 2; ++ni) {
                    int r = s * 64 + wn * 16 + ni * 8 + b_rowoff;
                    ldsm_x2(bf[ni], sbase + OFF_W + SWZ(r * 128 + kbyte + b_khalf * 16));
                }
#pragma unroll
                for (int mi = 0; mi < 4; ++mi)
#pragma unroll
                    for (int ni = 0; ni < 2; ++ni)
                        mma16816(zacc[mi][ni], af[mi], bf[ni]);
            }

            __syncthreads();
            // ---- gate + scale, stage bf16 z slab ----
#pragma unroll
            for (int mi = 0; mi < 4; ++mi) {
#pragma unroll
                for (int ni = 0; ni < 2; ++ni) {
                    const int pl = wn * 16 + ni * 8 + (lane & 3) * 2;
#pragma unroll
                    for (int rp = 0; rp < 2; ++rp) {
                        const int lrow = wm * 64 + mi * 16 + (lane >> 2) + rp * 8;
                        float2 g = Gt[(mi * 4 + ni * 2 + rp) * 32];
                        __nv_bfloat162 pk;
                        pk.x = __float2bfloat16(zacc[mi][ni][rp * 2]     * g.x * SCALE);
                        pk.y = __float2bfloat16(zacc[mi][ni][rp * 2 + 1] * g.y * SCALE);
                        *(uint32_t*)(dsm + OFF_Z + SWZ(lrow * 128 + pl * 2)) = *(uint32_t*)&pk;
                    }
                }
            }
            __syncthreads();

            // ---- o MMA: accumulate ----
#pragma unroll
            for (int ks2 = 0; ks2 < 4; ++ks2) {
                const int kbyte = ks2 * 32;
                uint32_t af2[4][4], bfo[ONI][2];
#pragma unroll
                for (int mi = 0; mi < 4; ++mi) {
                    int r = wm * 64 + mi * 16 + a_rowoff;
                    ldsm_x4(af2[mi], sbase + OFF_Z + SWZ(r * 128 + kbyte + a_khalf * 16));
                }
#pragma unroll
                for (int ni = 0; ni < ONI; ++ni) {
                    int rv = wn * (OW / 4) + ni * 8 + b_rowoff;
                    ldsm_x2(bfo[ni], sbase + OFF_V + s * VCB
                                     + SWZ(rv * 128 + kbyte + b_khalf * 16));
                }
#pragma unroll
                for (int mi = 0; mi < 4; ++mi)
#pragma unroll
                    for (int ni = 0; ni < ONI; ++ni)
                        mma16816(oacc[mi][ni], af2[mi], bfo[ni]);
            }
        }

        // ---- store o ----
        {
            const int mm = j % M;
#pragma unroll
            for (int mi = 0; mi < 4; ++mi) {
#pragma unroll
                for (int ni = 0; ni < ONI; ++ni) {
                    const int p0 = wn * (OW / 4) + ni * 8 + (lane & 3) * 2;
#pragma unroll
                    for (int rp = 0; rp < 2; ++rp) {
                        const int row = rowBase + wm * 64 + mi * 16 + (lane >> 2) + rp * 8;
                        float2 pk = {oacc[mi][ni][rp * 2], oacc[mi][ni][rp * 2 + 1]};
                        *(float2*)(gO + ((size_t)mm * NROWS + row) * OW + p0) = pk;
                        oacc[mi][ni][rp * 2] = 0.f;
                        oacc[mi][ni][rp * 2 + 1] = 0.f;
                    }
                }
            }
        }

        if (j + 2 < my_iters) issue_y(j + 2);
        cp_commit();
    }
}

// ================= fused tail: zo1 | zo2 | o0 in one launch =================
__global__ void __launch_bounds__(256, 2) tail_kernel(
    const float* __restrict__ c0, const float* __restrict__ X,
    const float* __restrict__ alphap, float* __restrict__ Out)
{
    const int phase = blockIdx.x / TAILG;
    const int bx    = blockIdx.x % TAILG;
    if (phase == 0)      zo_body<3, 1>(bx, TAILG);
    else if (phase == 1) zo_body<5, 2>(bx, TAILG);
    else                 mma_body<512, 128, 3, false>(bx, TAILG, 0, c0, X, alphap, Out);
}

// ================= final combine (smem transpose, coalesced) ================
__global__ void __launch_bounds__(256) combine_kernel(
    const float* __restrict__ x, const float* __restrict__ alphap,
    float* __restrict__ out)
{
    __shared__ float sO1[8][3][66];
    __shared__ float sO2[8][5][34];
    const int warp = threadIdx.x >> 5;
    const int lane = threadIdx.x & 31;
    const int row  = blockIdx.x * 8 + warp;
    const float ta = tanhf(alphap[0]);
    const float* xr = x + (size_t)row * DIN;
    float* outr = out + (size_t)row * DIN;

    // coalesced loads of this row's o1/o2 into smem
#pragma unroll
    for (int t = 0; t < 6; ++t) {          // 3*64 = 192 floats
        int idx = lane + t * 32;
        int m = idx >> 6, w = idx & 63;
        sO1[warp][m][w] = gO1[((size_t)m * NROWS + row) * 64 + w];
    }
#pragma unroll
    for (int t = 0; t < 5; ++t) {          // 5*32 = 160 floats
        int idx = lane + t * 32;
        int m = idx >> 5, w = idx & 31;
        sO2[warp][m][w] = gO2[((size_t)m * NROWS + row) * 32 + w];
    }
    __syncwarp();

#pragma unroll
    for (int t = 0; t < 6; ++t) {          // cols 128..319
        int c = 128 + lane + t * 32;
        int d = c - 128;
        outr[c] = xr[c] + ta * sO1[warp][d % 3][d / 3];
    }
#pragma unroll
    for (int t = 0; t < 5; ++t) {          // cols 320..479
        int c = 320 + lane + t * 32;
        int d = c - 320;
        outr[c] = xr[c] + ta * sO2[warp][d % 5][d / 5];
    }
}

// ================= launch =================
extern "C" void kernel_launch(void* const* d_in, const int* in_sizes, int n_in,
                              void* d_out, int out_size) {
    const float* x     = (const float*)d_in[0];
    const float* nw0   = (const float*)d_in[1];
    const float* nb0   = (const float*)d_in[2];
    const float* nw1   = (const float*)d_in[3];
    const float* nw2   = (const float*)d_in[4];
    const float* W0    = (const float*)d_in[5];
    const float* b0    = (const float*)d_in[6];
    const float* W1    = (const float*)d_in[7];
    const float* W2    = (const float*)d_in[8];
    const float* V0    = (const float*)d_in[9];
    const float* c0    = (const float*)d_in[10];
    const float* V1    = (const float*)d_in[11];
    const float* V2    = (const float*)d_in[12];
    const float* alpha = (const float*)d_in[13];
    float* out = (float*)d_out;

    constexpr int SM0   = 3 * 128 * 128 + 2 * 128 * 128;            // 80 KB (BRES)
    constexpr int SMZ1  = 256*128 + 4*64*128 + 2*128*128 + 128*128; // 112 KB
    cudaFuncSetAttribute(mma0_kernel, cudaFuncAttributeMaxDynamicSharedMemorySize, SM0);
    cudaFuncSetAttribute(tail_kernel, cudaFuncAttributeMaxDynamicSharedMemorySize, SMZ1);

    convert_w<<<880, 256>>>(W0, W1, W2, V0, V1, V2);
    norm_kernel<<<NROWS / 8, 256>>>(x, nw0, nb0, nw1, nw2);

    // stage 1: h0 -> silu/gates (B slab smem-resident)
    mma0_kernel<<<dim3(84, 7, 1), 256, SM0>>>(b0);
    // fused tail: zo1 + zo2 + o0 (all depend only on h0/norm)
    tail_kernel<<<3 * TAILG, 256, SMZ1>>>(c0, x, alpha, out);
    // residual gather for cols 128..479
    combine_kernel<<<NROWS / 8, 256>>>(x, alpha, out);
}

// round 17
// speedup vs baseline: 1.0325x; 1.0193x over previous
#include <cuda_runtime.h>
#include <cuda_bf16.h>
#include <math.h>
#include <cstdint>

#define NROWS 65536
#define DIN   480
#define H0D   512
#define GDIM  384
#define TAILG 296

// ================= scratch (device globals; no allocation) =================
__device__ __nv_bfloat16 gY0b[(size_t)NROWS * 128];       // y0 /sqrt(128)
__device__ __nv_bfloat16 gY1b[(size_t)3 * NROWS * 64];    // [m][row][64]
__device__ __nv_bfloat16 gY2b[(size_t)5 * NROWS * 64];    // [m][row][64] (only k<32 used)
__device__ __nv_bfloat16 gSb [(size_t)NROWS * 512];       // silu(h0)/sqrt(512)
// gates in MMA-native layout: [sg 0..5][tile 0..511][wid 0..7][idx16 0..15][lane 0..31] float2
__device__ float         gG3 [(size_t)6 * 512 * 128 * 64];
__device__ float         gO1 [(size_t)3 * NROWS * 64];    // o1 (scales folded)
__device__ float         gO2 [(size_t)5 * NROWS * 32];    // o2
// transposed bf16 weights  Wt[p][k]
__device__ __nv_bfloat16 gWt0[(size_t)896 * 128];
__device__ __nv_bfloat16 gWt1[(size_t)256 * 64];
__device__ __nv_bfloat16 gWt2[(size_t)128 * 64];          // k 32..63 zero (unused)
__device__ __nv_bfloat16 gVt0[(size_t)128 * 512];
__device__ __nv_bfloat16 gVt1[(size_t)64 * 256];
__device__ __nv_bfloat16 gVt2[(size_t)32 * 128];

// ================= helpers =================
__device__ __forceinline__ uint32_t smem_to_u32(const void* p) {
    uint32_t a;
    asm("{ .reg .u64 t; cvta.to.shared.u64 t, %1; cvt.u32.u64 %0, t; }" : "=r"(a) : "l"(p));
    return a;
}
#define SWZ(b) ((b) ^ (((b) >> 3) & 0x70))

__device__ __forceinline__ void cp16(uint32_t saddr, const void* g) {
    asm volatile("cp.async.cg.shared.global [%0], [%1], 16;" :: "r"(saddr), "l"(g));
}
__device__ __forceinline__ void cp_commit() {
    asm volatile("cp.async.commit_group;" ::: "memory");
}
__device__ __forceinline__ void cp_wait2() {
    asm volatile("cp.async.wait_group 2;" ::: "memory");
}
__device__ __forceinline__ void cp_wait1() {
    asm volatile("cp.async.wait_group 1;" ::: "memory");
}
__device__ __forceinline__ void prefetch_l1(const void* p) {
    asm volatile("prefetch.global.L1 [%0];" :: "l"(p));
}

__device__ __forceinline__ void ldsm_x4(uint32_t* r, uint32_t addr) {
    asm volatile("ldmatrix.sync.aligned.m8n8.x4.shared.b16 {%0,%1,%2,%3}, [%4];"
        : "=r"(r[0]), "=r"(r[1]), "=r"(r[2]), "=r"(r[3]) : "r"(addr));
}
__device__ __forceinline__ void ldsm_x2(uint32_t* r, uint32_t addr) {
    asm volatile("ldmatrix.sync.aligned.m8n8.x2.shared.b16 {%0,%1}, [%2];"
        : "=r"(r[0]), "=r"(r[1]) : "r"(addr));
}
__device__ __forceinline__ void mma16816(float* d, const uint32_t* a, const uint32_t* b) {
    asm volatile(
        "mma.sync.aligned.m16n8k16.row.col.f32.bf16.bf16.f32 "
        "{%0,%1,%2,%3}, {%4,%5,%6,%7}, {%8,%9}, {%0,%1,%2,%3};"
        : "+f"(d[0]), "+f"(d[1]), "+f"(d[2]), "+f"(d[3])
        : "r"(a[0]), "r"(a[1]), "r"(a[2]), "r"(a[3]), "r"(b[0]), "r"(b[1]));
}
__device__ __forceinline__ float sigmf(float v) { return 1.0f / (1.0f + __expf(-v)); }

// ================= kernel 0: fused convert+norm (independent phases) =======
__global__ void __launch_bounds__(256) init_kernel(
    const float* __restrict__ x,  const float* __restrict__ nw0,
    const float* __restrict__ nb0, const float* __restrict__ nw1,
    const float* __restrict__ nw2,
    const float* __restrict__ W0, const float* __restrict__ W1, const float* __restrict__ W2,
    const float* __restrict__ V0, const float* __restrict__ V1, const float* __restrict__ V2)
{
    if (blockIdx.x < 880) {
        // ---- weight convert+transpose ----
        int i = blockIdx.x * 256 + threadIdx.x;
        if (i < 114688) {                       // Wt0[896][128] <- W0[128][896]
            int p = i / 128, k = i % 128;
            gWt0[i] = __float2bfloat16(W0[k * 896 + p]);
        } else if ((i -= 114688) < 16384) {     // Wt1[256][64] <- W1[64][256]
            int p = i / 64, k = i % 64;
            gWt1[i] = __float2bfloat16(W1[k * 256 + p]);
        } else if ((i -= 16384) < 8192) {       // Wt2[128][64] <- W2[32][128], pad
            int p = i / 64, k = i % 64;
            gWt2[i] = (k < 32) ? __float2bfloat16(W2[k * 128 + p]) : __float2bfloat16(0.f);
        } else if ((i -= 8192) < 65536) {       // Vt0[128][512] <- V0[512][128]
            int p = i / 512, k = i % 512;
            gVt0[i] = __float2bfloat16(V0[k * 128 + p]);
        } else if ((i -= 65536) < 16384) {      // Vt1[64][256] <- V1[256][64]
            int p = i / 256, k = i % 256;
            gVt1[i] = __float2bfloat16(V1[k * 64 + p]);
        } else if ((i -= 16384) < 4096) {       // Vt2[32][128] <- V2[128][32]
            int p = i / 128, k = i % 128;
            gVt2[i] = __float2bfloat16(V2[k * 32 + p]);
        }
        return;
    }

    // ---- norms (one warp per row) ----
    const int warp = threadIdx.x >> 5;
    const int lane = threadIdx.x & 31;
    const int row  = (blockIdx.x - 880) * 8 + warp;
    const float* xr = x + (size_t)row * DIN;

    float4 v0 = ((const float4*)xr)[lane];
    float s = v0.x + v0.y + v0.z + v0.w;
    float q = v0.x*v0.x + v0.y*v0.y + v0.z*v0.z + v0.w*v0.w;
#pragma unroll
    for (int o = 16; o; o >>= 1) {
        s += __shfl_xor_sync(0xffffffffu, s, o);
        q += __shfl_xor_sync(0xffffffffu, q, o);
    }
    const float mu   = s * (1.0f / 128.0f);
    const float rstd = rsqrtf(q * (1.0f / 128.0f) - mu * mu + 1e-8f);

    float ss1 = 0.f, ss2 = 0.f;
    const float4* xr2 = (const float4*)(xr + 128);
#pragma unroll
    for (int j = lane; j < 88; j += 32) {
        float4 v = xr2[j];
        float d = v.x*v.x + v.y*v.y + v.z*v.z + v.w*v.w;
        if (j < 48) ss1 += d; else ss2 += d;
    }
#pragma unroll
    for (int o = 16; o; o >>= 1) {
        ss1 += __shfl_xor_sync(0xffffffffu, ss1, o);
        ss2 += __shfl_xor_sync(0xffffffffu, ss2, o);
    }
    const float inv = rsqrtf(0.5f * (ss1 * (1.f/192.f) + ss2 * (1.f/160.f)) + 1e-8f);

    const float invS0 = 0.08838834764831845f;
    float4 w = ((const float4*)nw0)[lane];
    float4 b = ((const float4*)nb0)[lane];
    __nv_bfloat16* y0 = gY0b + (size_t)row * 128 + lane * 4;
    y0[0] = __float2bfloat16(((v0.x - mu) * rstd * w.x + b.x) * invS0);
    y0[1] = __float2bfloat16(((v0.y - mu) * rstd * w.y + b.y) * invS0);
    y0[2] = __float2bfloat16(((v0.z - mu) * rstd * w.z + b.z) * invS0);
    y0[3] = __float2bfloat16(((v0.w - mu) * rstd * w.w + b.w) * invS0);

#pragma unroll
    for (int t = 0; t < 2; ++t) {
        int u = lane + t * 32;
        float c = inv * nw1[u] * 0.125f;
#pragma unroll
        for (int m = 0; m < 3; ++m)
            gY1b[((size_t)m * NROWS + row) * 64 + u] = __float2bfloat16(xr[128 + 3*u + m] * c);
    }
    {
        int u = lane;
        float c = inv * nw2[u] * 0.17677669529663689f;
#pragma unroll
        for (int m = 0; m < 5; ++m)
            gY2b[((size_t)m * NROWS + row) * 64 + u] =
                __float2bfloat16(xr[320 + 5*u + m] * c);
    }
}

// ================= HMMA GEMM body (persistent + cp.async pipeline) =========
// EPI 0: h0 -> silu/gate (BRES: B slab smem-resident) ; EPI 3: o0 + residual.
// PDLSYNC: wait on prior grid before touching dependent inputs.
template<int KdA, int NT, int EPI, bool BRES, bool PDLSYNC>
__device__ __forceinline__ void mma_body(
    int t0, int tstr, int pb,
    const float* __restrict__ bias, const float* __restrict__ X,
    const float* __restrict__ alphap, float* __restrict__ Out)
{
    constexpr int NCH   = KdA / 64;
    constexpr int WT_N  = NT / 4;
    constexpr int NI    = WT_N / 8;
    constexpr int MI    = 4;
    constexpr int SAB   = 128 * 128;                 // A chunk bytes
    constexpr int SBB   = NT * 128;                  // B chunk bytes
    constexpr int STAGE = BRES ? SAB : (SAB + SBB);  // per-pipeline-stage bytes
    constexpr int OFF_B = 3 * SAB;                   // BRES: resident B planes
    constexpr int DEPTH = 3;
    constexpr int NTILES = NROWS / 128;

    if (PDLSYNC) cudaGridDependencySynchronize();    // A (gSb) is dependent

    extern __shared__ __align__(16) char dsm[];
    const uint32_t sbase = smem_to_u32(dsm);

    const int tid  = threadIdx.x;
    const int lane = tid & 31;
    const int wid  = tid >> 5;
    const int wm   = wid >> 2;
    const int wn   = wid & 3;

    const __nv_bfloat16* gA  = (EPI == 0) ? gY0b : gSb;
    const __nv_bfloat16* gBw = (EPI == 0) ? gWt0 : gVt0;

    const int my_tiles = (t0 < NTILES) ? ((NTILES - 1 - t0) / tstr + 1) : 0;
    const int my_iters = my_tiles * NCH;

    auto issue_load = [&](int idx) {
        const int tile = t0 + (idx / NCH) * tstr;
        const int ch   = idx % NCH;
        const uint32_t st = sbase + (uint32_t)(idx % DEPTH) * STAGE;
        const __nv_bfloat16* Ab = gA + (size_t)(tile * 128) * KdA + ch * 64;
#pragma unroll
        for (int t = 0; t < 4; ++t) {
            int i2 = tid + t * 256;
            int r = i2 >> 3, v = i2 & 7;
            cp16(st + SWZ(r * 128 + v * 16), Ab + (size_t)r * KdA + v * 8);
        }
        if (!BRES) {
            const __nv_bfloat16* Bb = gBw + (size_t)pb * KdA + ch * 64;
#pragma unroll
            for (int t = 0; t < NT / 32; ++t) {
                int i2 = tid + t * 256;
                int r = i2 >> 3, v = i2 & 7;
                cp16(st + SAB + SWZ(r * 128 + v * 16), Bb + (size_t)r * KdA + v * 8);
            }
        }
    };

    float acc[MI][NI][4];
#pragma unroll
    for (int i = 0; i < MI; ++i)
#pragma unroll
        for (int j = 0; j < NI; ++j)
#pragma unroll
            for (int r = 0; r < 4; ++r) acc[i][j][r] = 0.f;

    const int a_rowoff = (lane & 7) + ((lane >> 3) & 1) * 8;
    const int a_khalf  = lane >> 4;
    const int laneb    = lane & 15;
    const int b_rowoff = laneb & 7;
    const int b_khalf  = laneb >> 3;
    const float ta = (EPI == 3) ? tanhf(alphap[0]) : 0.0f;

    // prologue: BRES loads resident B (all NCH chunks) in group 0.
    if (BRES && my_iters > 0) {
        const __nv_bfloat16* Bb = gBw + (size_t)pb * KdA;
#pragma unroll
        for (int t = 0; t < (NT * NCH) / 32; ++t) {
            int i2 = tid + t * 256;
            int r = i2 >> 4, v = i2 & 15;         // r < NT, v < 16
            int ch = v >> 3, v8 = v & 7;
            cp16(sbase + OFF_B + (uint32_t)ch * SBB + SWZ(r * 128 + v8 * 16),
                 Bb + (size_t)r * KdA + ch * 64 + v8 * 8);
        }
    }
#pragma unroll
    for (int i = 0; i < DEPTH; ++i) {
        if (i < my_iters) issue_load(i);
        cp_commit();
    }

#pragma unroll 1
    for (int it = 0; it < my_iters; ++it) {
        cp_wait2();
        __syncthreads();

        const uint32_t st_a = sbase + (uint32_t)(it % DEPTH) * STAGE;
        const uint32_t st_b = BRES ? (sbase + OFF_B + (uint32_t)(it % NCH) * SBB)
                                   : (st_a + SAB);
#pragma unroll
        for (int ks = 0; ks < 4; ++ks) {
            const int kbyte = ks * 32;
            uint32_t af[MI][4], bf[NI][2];
#pragma unroll
            for (int mi = 0; mi < MI; ++mi) {
                int r = wm * 64 + mi * 16 + a_rowoff;
                ldsm_x4(af[mi], st_a + SWZ(r * 128 + kbyte + a_khalf * 16));
            }
#pragma unroll
            for (int ni = 0; ni < NI; ++ni) {
                int r = wn * WT_N + ni * 8 + b_rowoff;
                ldsm_x2(bf[ni], st_b + SWZ(r * 128 + kbyte + b_khalf * 16));
            }
#pragma unroll
            for (int mi = 0; mi < MI; ++mi)
#pragma unroll
                for (int ni = 0; ni < NI; ++ni)
                    mma16816(acc[mi][ni], af[mi], bf[ni]);
        }

        if ((it % NCH) == NCH - 1) {
            const int tile = t0 + (it / NCH) * tstr;
            const int rowBase = tile * 128;
#pragma unroll
            for (int mi = 0; mi < MI; ++mi) {
#pragma unroll
                for (int ni = 0; ni < NI; ++ni) {
                    const int p0 = pb + wn * WT_N + ni * 8 + (lane & 3) * 2;
#pragma unroll
                    for (int rp = 0; rp < 2; ++rp) {
                        const int row = rowBase + wm * 64 + mi * 16 + (lane >> 2) + rp * 8;
                        float v0 = acc[mi][ni][rp * 2];
                        float v1 = acc[mi][ni][rp * 2 + 1];
                        if (EPI == 0) {
                            float h0 = v0 + bias[p0];
                            float h1 = v1 + bias[p0 + 1];
                            if (p0 < H0D) {   // uniform per block
                                __nv_bfloat162 pk;
                                pk.x = __float2bfloat16(h0 * sigmf(h0) * 0.04419417382415922f);
                                pk.y = __float2bfloat16(h1 * sigmf(h1) * 0.04419417382415922f);
                                *(__nv_bfloat162*)(gSb + (size_t)row * 512 + p0) = pk;
                            } else {
                                // gate -> MMA-native layout for zo consumers
                                float2 pk = {sigmf(h0), sigmf(h1)};
                                int gcol = p0 - H0D;
                                int sg = gcol >> 6, pl = gcol & 63;
                                int lr = row & 127;
                                int wm_z = lr >> 6, mi_z = (lr >> 4) & 3,
                                    rp_z = (lr >> 3) & 1, lq = lr & 7;
                                int wn_z = pl >> 4, ni_z = (pl >> 3) & 1,
                                    l2 = (pl >> 1) & 3;
                                int wid_z = wm_z * 4 + wn_z;
                                int lane_z = lq * 4 + l2;
                                int idx = mi_z * 4 + ni_z * 2 + rp_z;
                                size_t off = (((size_t)sg * NTILES + tile) << 13)
                                           + wid_z * 1024 + (idx * 32 + lane_z) * 2;
                                *(float2*)(gG3 + off) = pk;
                            }
                        } else {
                            size_t o = (size_t)row * DIN + p0;
                            float2 xv = *(const float2*)(X + o);
                            float2 pk = {xv.x + ta * (v0 + bias[p0]),
                                         xv.y + ta * (v1 + bias[p0 + 1])};
                            *(float2*)(Out + o) = pk;
                        }
                        acc[mi][ni][rp * 2] = 0.f;
                        acc[mi][ni][rp * 2 + 1] = 0.f;
                    }
                }
            }
        }

        __syncthreads();
        if (it + DEPTH < my_iters) issue_load(it + DEPTH);
        cp_commit();
    }
}

__global__ void __launch_bounds__(256, 2) mma0_kernel(const float* __restrict__ bias) {
    mma_body<128, 128, 0, true, false>(blockIdx.x, gridDim.x, blockIdx.y * 128,
                                       bias, nullptr, nullptr, nullptr);
}

// ================= fused z + down-projection body per spectral branch ======
// (zMMA -> stage -> oMMA per slab.) Prologue (weights/Vt/Y) is independent of
// the prior grid, so under PDL we issue it before cudaGridDependencySynchronize.
template<int M, int BR>   // BR=1: H=256,K=64 ; BR=2: H=128,K=32
__device__ __forceinline__ void zo_body(int t0, int tstr)
{
    constexpr int NSLAB  = (BR == 1) ? 4 : 2;       // H / 64
    constexpr int KSY    = (BR == 1) ? 4 : 2;       // k16 steps of the z GEMM
    constexpr int OW     = (BR == 1) ? 64 : 32;     // o columns
    constexpr int ONI    = OW / 32;                 // 2 / 1
    constexpr int SGOF   = (BR == 1) ? 0 : 4;       // global gate-slab offset
    constexpr int WROWS  = (BR == 1) ? 256 : 128;
    constexpr int VROWS  = OW;
    constexpr int VCB    = VROWS * 128;             // bytes per Vt chunk
    constexpr int OFF_W  = 0;
    constexpr int OFF_V  = OFF_W + WROWS * 128;
    constexpr int OFF_Y  = OFF_V + NSLAB * VCB;
    constexpr int YB     = 128 * 128;
    constexpr int OFF_Z  = OFF_Y + 2 * YB;
    constexpr int NTILES = NROWS / 128;

    extern __shared__ __align__(16) char dsm[];
    const uint32_t sbase = smem_to_u32(dsm);

    const int tid  = threadIdx.x;
    const int wid  = tid >> 5;
    const int lane = tid & 31;
    const int wm   = wid >> 2;
    const int wn   = wid & 3;

    const __nv_bfloat16* gA  = (BR == 1) ? gY1b : gY2b;
    const __nv_bfloat16* gWt = (BR == 1) ? gWt1 : gWt2;
    const __nv_bfloat16* gVt = (BR == 1) ? gVt1 : gVt2;
    float* gO = (BR == 1) ? gO1 : gO2;
    const float SCALE = (BR == 1) ? 0.0625f : 0.08838834764831845f;

    const int my_tiles = (t0 < NTILES) ? ((NTILES - 1 - t0) / tstr + 1) : 0;
    const int my_iters = my_tiles * M;

    auto issue_y = [&](int j) {
        const int tile = t0 + (j / M) * tstr;
        const int mm   = j % M;
        const __nv_bfloat16* Ab = gA + ((size_t)mm * NROWS + tile * 128) * 64;
        const uint32_t yb = sbase + OFF_Y + (uint32_t)(j & 1) * YB;
        if (KSY == 4) {
#pragma unroll
            for (int t = 0; t < 4; ++t) {
                int i2 = tid + t * 256;
                int r = i2 >> 3, v = i2 & 7;
                cp16(yb + SWZ(r * 128 + v * 16), Ab + (size_t)r * 64 + v * 8);
            }
        } else {
#pragma unroll
            for (int t = 0; t < 2; ++t) {
                int i2 = tid + t * 256;
                int r = i2 >> 2, v = i2 & 3;
                cp16(yb + SWZ(r * 128 + v * 16), Ab + (size_t)r * 64 + v * 8);
            }
        }
    };

    // prologue: weights + Vt + Y(0) in group0, Y(1) in group1 — all independent
    if (my_iters > 0) {
        if (BR == 1) {
#pragma unroll
            for (int t = 0; t < 8; ++t) {       // Wt1: 256 rows x 8 xfers
                int i2 = tid + t * 256;
                int r = i2 >> 3, v = i2 & 7;
                cp16(sbase + OFF_W + SWZ(r * 128 + v * 16), gWt + (size_t)r * 64 + v * 8);
            }
#pragma unroll
            for (int t = 0; t < 8; ++t) {       // Vt1: 4 chunks x 64 rows x 8 xfers
                int i2 = tid + t * 256;
                int s = i2 >> 9, p = (i2 >> 3) & 63, v = i2 & 7;
                cp16(sbase + OFF_V + s * VCB + SWZ(p * 128 + v * 16),
                     gVt + (size_t)p * 256 + s * 64 + v * 8);
            }
        } else {
#pragma unroll
            for (int t = 0; t < 2; ++t) {       // Wt2: 128 rows x 4 xfers (K=32)
                int i2 = tid + t * 256;
                int r = i2 >> 2, v = i2 & 3;
                cp16(sbase + OFF_W + SWZ(r * 128 + v * 16), gWt + (size_t)r * 64 + v * 8);
            }
#pragma unroll
            for (int t = 0; t < 2; ++t) {       // Vt2: 2 chunks x 32 rows x 8 xfers
                int i2 = tid + t * 256;
                int s = i2 >> 8, p = (i2 >> 3) & 31, v = i2 & 7;
                cp16(sbase + OFF_V + s * VCB + SWZ(p * 128 + v * 16),
                     gVt + (size_t)p * 128 + s * 64 + v * 8);
            }
        }
        issue_y(0);
    }
    cp_commit();
    if (1 < my_iters) issue_y(1);
    cp_commit();

    // wait for mma0's gates (gG3) before the main loop touches them
    cudaGridDependencySynchronize();

    float oacc[4][ONI][4];
#pragma unroll
    for (int i = 0; i < 4; ++i)
#pragma unroll
        for (int j = 0; j < ONI; ++j)
#pragma unroll
            for (int r = 0; r < 4; ++r) oacc[i][j][r] = 0.f;

    const int a_rowoff = (lane & 7) + ((lane >> 3) & 1) * 8;
    const int a_khalf  = lane >> 4;
    const int laneb    = lane & 15;
    const int b_rowoff = laneb & 7;
    const int b_khalf  = laneb >> 3;

#pragma unroll 1
    for (int j = 0; j < my_iters; ++j) {
        cp_wait1();
        __syncthreads();

        const uint32_t yb = sbase + OFF_Y + (uint32_t)(j & 1) * YB;
        const int tile = t0 + (j / M) * tstr;
        const int rowBase = tile * 128;

#pragma unroll 1
        for (int s = 0; s < NSLAB; ++s) {
            const size_t gblk = ((size_t)(SGOF + s) * NTILES + tile) << 13;  // floats
            const float2* Gt = (const float2*)(gG3 + gblk) + wid * 512 + lane;
            prefetch_l1((const char*)(gG3 + gblk) + wid * 4096 + lane * 128);

            float zacc[4][2][4];
#pragma unroll
            for (int i = 0; i < 4; ++i)
#pragma unroll
                for (int n = 0; n < 2; ++n)
#pragma unroll
                    for (int r = 0; r < 4; ++r) zacc[i][n][r] = 0.f;

            // ---- z slab MMA ----
#pragma unroll
            for (int ks = 0; ks < KSY; ++ks) {
                const int kbyte = ks * 32;
                uint32_t af[4][4], bf[2][2];
#pragma unroll
                for (int mi = 0; mi < 4; ++mi) {
                    int r = wm * 64 + mi * 16 + a_rowoff;
                    ldsm_x4(af[mi], yb + SWZ(r * 128 + kbyte + a_khalf * 16));
                }
#pragma unroll
                for (int ni = 0; ni < 2; ++ni) {
                    int r = s * 64 + wn * 16 + ni * 8 + b_rowoff;
                    ldsm_x2(bf[ni], sbase + OFF_W + SWZ(r * 128 + kbyte + b_khalf * 16));
                }
#pragma unroll
                for (int mi = 0; mi < 4; ++mi)
#pragma unroll
                    for (int ni = 0; ni < 2; ++ni)
                        mma16816(zacc[mi][ni], af[mi], bf[ni]);
            }

            __syncthreads();
            // ---- gate + scale, stage bf16 z slab ----
#pragma unroll
            for (int mi = 0; mi < 4; ++mi) {
#pragma unroll
                for (int ni = 0; ni < 2; ++ni) {
                    const int pl = wn * 16 + ni * 8 + (lane & 3) * 2;
#pragma unroll
                    for (int rp = 0; rp < 2; ++rp) {
                        const int lrow = wm * 64 + mi * 16 + (lane >> 2) + rp * 8;
                        float2 g = Gt[(mi * 4 + ni * 2 + rp) * 32];
                        __nv_bfloat162 pk;
                        pk.x = __float2bfloat16(zacc[mi][ni][rp * 2]     * g.x * SCALE);
                        pk.y = __float2bfloat16(zacc[mi][ni][rp * 2 + 1] * g.y * SCALE);
                        *(uint32_t*)(dsm + OFF_Z + SWZ(lrow * 128 + pl * 2)) = *(uint32_t*)&pk;
                    }
                }
            }
            __syncthreads();

            // ---- o MMA: accumulate ----
#pragma unroll
            for (int ks2 = 0; ks2 < 4; ++ks2) {
                const int kbyte = ks2 * 32;
                uint32_t af2[4][4], bfo[ONI][2];
#pragma unroll
                for (int mi = 0; mi < 4; ++mi) {
                    int r = wm * 64 + mi * 16 + a_rowoff;
                    ldsm_x4(af2[mi], sbase + OFF_Z + SWZ(r * 128 + kbyte + a_khalf * 16));
                }
#pragma unroll
                for (int ni = 0; ni < ONI; ++ni) {
                    int rv = wn * (OW / 4) + ni * 8 + b_rowoff;
                    ldsm_x2(bfo[ni], sbase + OFF_V + s * VCB
                                     + SWZ(rv * 128 + kbyte + b_khalf * 16));
                }
#pragma unroll
                for (int mi = 0; mi < 4; ++mi)
#pragma unroll
                    for (int ni = 0; ni < ONI; ++ni)
                        mma16816(oacc[mi][ni], af2[mi], bfo[ni]);
            }
        }

        // ---- store o ----
        {
            const int mm = j % M;
#pragma unroll
            for (int mi = 0; mi < 4; ++mi) {
#pragma unroll
                for (int ni = 0; ni < ONI; ++ni) {
                    const int p0 = wn * (OW / 4) + ni * 8 + (lane & 3) * 2;
#pragma unroll
                    for (int rp = 0; rp < 2; ++rp) {
                        const int row = rowBase + wm * 64 + mi * 16 + (lane >> 2) + rp * 8;
                        float2 pk = {oacc[mi][ni][rp * 2], oacc[mi][ni][rp * 2 + 1]};
                        *(float2*)(gO + ((size_t)mm * NROWS + row) * OW + p0) = pk;
                        oacc[mi][ni][rp * 2] = 0.f;
                        oacc[mi][ni][rp * 2 + 1] = 0.f;
                    }
                }
            }
        }

        if (j + 2 < my_iters) issue_y(j + 2);
        cp_commit();
    }
}

// ================= fused tail: zo1 | zo2 | o0 in one launch =================
__global__ void __launch_bounds__(256, 2) tail_kernel(
    const float* __restrict__ c0, const float* __restrict__ X,
    const float* __restrict__ alphap, float* __restrict__ Out)
{
    const int phase = blockIdx.x / TAILG;
    const int bx    = blockIdx.x % TAILG;
    if (phase == 0)      zo_body<3, 1>(bx, TAILG);
    else if (phase == 1) zo_body<5, 2>(bx, TAILG);
    else                 mma_body<512, 128, 3, false, true>(bx, TAILG, 0, c0, X, alphap, Out);
}

// ================= final combine (x prefetched pre-sync, gO post-sync) ======
__global__ void __launch_bounds__(256) combine_kernel(
    const float* __restrict__ x, const float* __restrict__ alphap,
    float* __restrict__ out)
{
    __shared__ float sO1[8][3][66];
    __shared__ float sO2[8][5][34];
    const int warp = threadIdx.x >> 5;
    const int lane = threadIdx.x & 31;
    const int row  = blockIdx.x * 8 + warp;
    const float* xr = x + (size_t)row * DIN;
    float* outr = out + (size_t)row * DIN;

    // x is independent of the tail: prefetch before the grid sync
    float xv[11];
#pragma unroll
    for (int t = 0; t < 11; ++t)
        xv[t] = xr[128 + lane + t * 32];
    const float ta = tanhf(alphap[0]);

    cudaGridDependencySynchronize();   // wait for tail's gO1/gO2

    // coalesced loads of this row's o1/o2 into smem
#pragma unroll
    for (int t = 0; t < 6; ++t) {          // 3*64 = 192 floats
        int idx = lane + t * 32;
        int m = idx >> 6, w = idx & 63;
        sO1[warp][m][w] = gO1[((size_t)m * NROWS + row) * 64 + w];
    }
#pragma unroll
    for (int t = 0; t < 5; ++t) {          // 5*32 = 160 floats
        int idx = lane + t * 32;
        int m = idx >> 5, w = idx & 31;
        sO2[warp][m][w] = gO2[((size_t)m * NROWS + row) * 32 + w];
    }
    __syncwarp();

#pragma unroll
    for (int t = 0; t < 6; ++t) {          // cols 128..319
        int c = 128 + lane + t * 32;
        int d = c - 128;
        outr[c] = xv[t] + ta * sO1[warp][d % 3][d / 3];
    }
#pragma unroll
    for (int t = 0; t < 5; ++t) {          // cols 320..479
        int c = 320 + lane + t * 32;
        int d = c - 320;
        outr[c] = xv[6 + t] + ta * sO2[warp][d % 5][d / 5];
    }
}

// ================= launch =================
extern "C" void kernel_launch(void* const* d_in, const int* in_sizes, int n_in,
                              void* d_out, int out_size) {
    const float* x     = (const float*)d_in[0];
    const float* nw0   = (const float*)d_in[1];
    const float* nb0   = (const float*)d_in[2];
    const float* nw1   = (const float*)d_in[3];
    const float* nw2   = (const float*)d_in[4];
    const float* W0    = (const float*)d_in[5];
    const float* b0    = (const float*)d_in[6];
    const float* W1    = (const float*)d_in[7];
    const float* W2    = (const float*)d_in[8];
    const float* V0    = (const float*)d_in[9];
    const float* c0    = (const float*)d_in[10];
    const float* V1    = (const float*)d_in[11];
    const float* V2    = (const float*)d_in[12];
    const float* alpha = (const float*)d_in[13];
    float* out = (float*)d_out;

    constexpr int SM0   = 3 * 128 * 128 + 2 * 128 * 128;            // 80 KB (BRES)
    constexpr int SMZ1  = 256*128 + 4*64*128 + 2*128*128 + 128*128; // 112 KB
    cudaFuncSetAttribute(mma0_kernel, cudaFuncAttributeMaxDynamicSharedMemorySize, SM0);
    cudaFuncSetAttribute(tail_kernel, cudaFuncAttributeMaxDynamicSharedMemorySize, SMZ1);

    // convert + norm fused (independent phases)
    init_kernel<<<880 + NROWS / 8, 256>>>(x, nw0, nb0, nw1, nw2,
                                          W0, W1, W2, V0, V1, V2);

    // stage 1: h0 -> silu/gates (B slab smem-resident)
    mma0_kernel<<<dim3(84, 7, 1), 256, SM0>>>(b0);

    // fused tail with PDL: prologues overlap mma0's drain
    {
        cudaLaunchConfig_t cfg = {};
        cfg.gridDim = dim3(3 * TAILG, 1, 1);
        cfg.blockDim = dim3(256, 1, 1);
        cfg.dynamicSmemBytes = SMZ1;
        cfg.stream = 0;
        cudaLaunchAttribute attr[1];
        attr[0].id = cudaLaunchAttributeProgrammaticStreamSerialization;
        attr[0].val.programmaticStreamSerializationAllowed = 1;
        cfg.attrs = attr;
        cfg.numAttrs = 1;
        cudaLaunchKernelEx(&cfg, tail_kernel, c0, x, alpha, out);
    }

    // residual gather with PDL: x prefetch overlaps tail's drain
    {
        cudaLaunchConfig_t cfg = {};
        cfg.gridDim = dim3(NROWS / 8, 1, 1);
        cfg.blockDim = dim3(256, 1, 1);
        cfg.dynamicSmemBytes = 0;
        cfg.stream = 0;
        cudaLaunchAttribute attr[1];
        attr[0].id = cudaLaunchAttributeProgrammaticStreamSerialization;
        attr[0].val.programmaticStreamSerializationAllowed = 1;
        cfg.attrs = attr;
        cfg.numAttrs = 1;
        cudaLaunchKernelEx(&cfg, combine_kernel, x, alpha, out);
    }
}